// round 1
// baseline (speedup 1.0000x reference)
#include <cuda_runtime.h>
#include <math_constants.h>

#define NB   32
#define LT   2048
#define CC   128
#define J    16          // number of chunks
#define TC   (LT / J)    // 128 timesteps per chunk
#define OUTW 1172        // 3*384 + 20
#define NLC  ((size_t)NB * LT * CC)          // 8,388,608
#define OUT_ELEMS ((size_t)NB * LT * OUTW)   // 76,808,192

// chunk aggregates: [3][32][J][128]
__device__ float g_cmax[3 * NB * J * CC];
__device__ int   g_carg[3 * NB * J * CC];
__device__ float g_csum[3 * NB * J * CC];
__device__ float g_dmlp[NB * 20];

// ---------------- tiny demographic MLP: [32,8] -> relu(40) -> relu(20) -------
__global__ void mlp_kernel(const float* __restrict__ dem,
                           const float* __restrict__ W1, const float* __restrict__ b1,
                           const float* __restrict__ W2, const float* __restrict__ b2) {
    int n = threadIdx.x;
    if (n >= NB) return;
    float d[8];
#pragma unroll
    for (int k = 0; k < 8; ++k) d[k] = dem[n * 8 + k];
    float h[40];
#pragma unroll
    for (int o = 0; o < 40; ++o) {
        float s = b1[o];
#pragma unroll
        for (int k = 0; k < 8; ++k) s = fmaf(d[k], W1[k * 40 + o], s);
        h[o] = fmaxf(s, 0.f);
    }
#pragma unroll
    for (int o = 0; o < 20; ++o) {
        float s = b2[o];
#pragma unroll
        for (int k = 0; k < 40; ++k) s = fmaf(h[k], W2[k * 20 + o], s);
        g_dmlp[n * 20 + o] = fmaxf(s, 0.f);
    }
}

// ---------------- pass A: per-chunk aggregates --------------------------------
__global__ void __launch_bounds__(CC) agg_kernel(const float* __restrict__ x0,
                                                 const float* __restrict__ x1,
                                                 const float* __restrict__ x2) {
    const int j = blockIdx.x, n = blockIdx.y, i = blockIdx.z;
    const int c = threadIdx.x;
    const float* x = (i == 0) ? x0 : (i == 1) ? x1 : x2;
    const float* p = x + ((size_t)n * LT + (size_t)j * TC) * CC + c;

    float m = -CUDART_INF_F, s = 0.f;
    int a = 0;
#pragma unroll 8
    for (int t = 0; t < TC; ++t) {
        float v = p[(size_t)t * CC];
        s += v;
        if (v > m) { m = v; a = j * TC + t; }   // strict > => earliest index wins
    }
    int idx = ((i * NB + n) * J + j) * CC + c;
    g_cmax[idx] = m;
    g_carg[idx] = a;
    g_csum[idx] = s;
}

// ---------------- pass B: fold prefix, emit all outputs -----------------------
__global__ void __launch_bounds__(CC) emit_kernel(const float* __restrict__ x0,
                                                  const float* __restrict__ x1,
                                                  const float* __restrict__ x2,
                                                  float* __restrict__ out) {
    const int j = blockIdx.x, n = blockIdx.y, i = blockIdx.z;
    const int c = threadIdx.x;
    const float* x = (i == 0) ? x0 : (i == 1) ? x1 : x2;

    // exclusive prefix over earlier chunks (reads hit L2; J small)
    float pm = -CUDART_INF_F, ps = 0.f;
    int pa = 0;
    const int base = ((i * NB + n) * J) * CC + c;
    for (int k = 0; k < j; ++k) {
        float m = g_cmax[base + k * CC];
        if (m > pm) { pm = m; pa = g_carg[base + k * CC]; }
        ps += g_csum[base + k * CC];
    }

    const size_t row0 = (size_t)n * LT + (size_t)j * TC;  // first global t of this chunk
    const float* p = x + row0 * CC + c;

    float* orow = out + row0 * OUTW + (size_t)i * 384 + c;
    size_t ind_off = OUT_ELEMS + (size_t)i * NLC + row0 * CC + c;
    size_t act_off = ind_off + 3 * NLC;

    const float inv_L = 1.0f / (float)LT;

#pragma unroll 4
    for (int t = 0; t < TC; ++t) {
        const int T = j * TC + t;
        float v = p[(size_t)t * CC];
        ps += v;
        if (v > pm) { pm = v; pa = T; }

        // p_max: windows with t < L-1 still contain left-pad zeros
        float pmax = (T < LT - 1) ? fmaxf(pm, 0.f) : pm;
        // index: if a pad zero wins the window max, point at first pad slot
        float ind = (T < LT - 1 && pm < 0.f) ? (float)(T - (LT - 1)) : (float)pa;
        float pavg = ps * inv_L;
        float psum = __fdividef(ps, (float)(T + 1));

        orow[0]   = pmax;
        orow[128] = pavg;
        orow[256] = psum;
        out[ind_off] = ind;
        out[act_off] = pmax;

        orow += OUTW;
        ind_off += CC;
        act_off += CC;
    }

    // demographic broadcast columns [1152:1172) — written once (by i==0 blocks)
    if (i == 0) {
        float dv[20];
#pragma unroll
        for (int k = 0; k < 20; ++k) dv[k] = g_dmlp[n * 20 + k];
        for (int q = threadIdx.x; q < TC * 20; q += CC) {
            int t = q / 20, k = q % 20;
            out[(row0 + t) * OUTW + 1152 + k] = dv[k];
        }
    }
}

extern "C" void kernel_launch(void* const* d_in, const int* in_sizes, int n_in,
                              void* d_out, int out_size) {
    const float* inp0 = (const float*)d_in[0];
    const float* inp1 = (const float*)d_in[1];
    const float* inp2 = (const float*)d_in[2];
    const float* dem  = (const float*)d_in[3];
    const float* W1   = (const float*)d_in[4];
    const float* b1   = (const float*)d_in[5];
    const float* W2   = (const float*)d_in[6];
    const float* b2   = (const float*)d_in[7];
    float* out = (float*)d_out;

    mlp_kernel<<<1, 32>>>(dem, W1, b1, W2, b2);
    dim3 grid(J, NB, 3);
    agg_kernel<<<grid, CC>>>(inp0, inp1, inp2);
    emit_kernel<<<grid, CC>>>(inp0, inp1, inp2, out);
}

// round 2
// speedup vs baseline: 1.0229x; 1.0229x over previous
#include <cuda_runtime.h>
#include <math_constants.h>

#define NB   32
#define LT   2048
#define CC   128
#define J    16          // chunks along L
#define TC   (LT / J)    // 128 rows per chunk
#define OUTW 1172        // 3*384 + 20
#define NLC  ((size_t)NB * LT * CC)          // 8,388,608
#define OUT_ELEMS ((size_t)NB * LT * OUTW)   // 76,808,192

// chunk aggregates: [3][32][J][128] (c contiguous)
__device__ float g_cmax[3 * NB * J * CC];
__device__ int   g_carg[3 * NB * J * CC];
__device__ float g_csum[3 * NB * J * CC];

// ---------------- pass A: per-chunk aggregates (warp per chunk, float4/lane) --
__global__ void __launch_bounds__(128) agg_kernel(const float* __restrict__ x0,
                                                  const float* __restrict__ x1,
                                                  const float* __restrict__ x2) {
    const int w = threadIdx.x >> 5;              // warp -> chunk within block
    const int l = threadIdx.x & 31;              // lane -> 4 channels
    const int j = blockIdx.x * 4 + w;
    const int n = blockIdx.y, i = blockIdx.z;
    const float* x = (i == 0) ? x0 : (i == 1) ? x1 : x2;
    const float4* p = (const float4*)(x + ((size_t)n * LT + (size_t)j * TC) * CC) + l;

    float m0 = -CUDART_INF_F, m1 = m0, m2 = m0, m3 = m0;
    float s0 = 0.f, s1 = 0.f, s2 = 0.f, s3 = 0.f;
    int a0 = 0, a1 = 0, a2 = 0, a3 = 0;
#pragma unroll 4
    for (int t = 0; t < TC; ++t) {
        float4 v = p[t * 32];
        const int T = j * TC + t;
        s0 += v.x; s1 += v.y; s2 += v.z; s3 += v.w;
        if (v.x > m0) { m0 = v.x; a0 = T; }
        if (v.y > m1) { m1 = v.y; a1 = T; }
        if (v.z > m2) { m2 = v.z; a2 = T; }
        if (v.w > m3) { m3 = v.w; a3 = T; }
    }
    const int idx = ((i * NB + n) * J + j) * CC + 4 * l;
    *(float4*)&g_cmax[idx] = make_float4(m0, m1, m2, m3);
    *(int4*)  &g_carg[idx] = make_int4(a0, a1, a2, a3);
    *(float4*)&g_csum[idx] = make_float4(s0, s1, s2, s3);
}

// ---------------- pass B: fold prefix, emit all outputs -----------------------
__global__ void __launch_bounds__(128) emit_kernel(const float* __restrict__ x0,
                                                   const float* __restrict__ x1,
                                                   const float* __restrict__ x2,
                                                   const float* __restrict__ dem,
                                                   const float* __restrict__ W1,
                                                   const float* __restrict__ b1,
                                                   const float* __restrict__ W2,
                                                   const float* __restrict__ b2,
                                                   float* __restrict__ out) {
    const int w = threadIdx.x >> 5;
    const int l = threadIdx.x & 31;
    const int j = blockIdx.x * 4 + w;
    const int n = blockIdx.y, i = blockIdx.z;
    const float* x = (i == 0) ? x0 : (i == 1) ? x1 : x2;

    // -- demographic MLP (only needed by i==0 blocks; recomputed per block) ----
    __shared__ float h_sh[40];
    __shared__ float d_sh[20];
    if (i == 0 && threadIdx.x < 40) {
        const int o = threadIdx.x;
        float s = b1[o];
#pragma unroll
        for (int k = 0; k < 8; ++k) s = fmaf(dem[n * 8 + k], W1[k * 40 + o], s);
        h_sh[o] = fmaxf(s, 0.f);
    }
    __syncthreads();
    if (i == 0 && threadIdx.x < 20) {
        const int o = threadIdx.x;
        float s = b2[o];
#pragma unroll
        for (int k = 0; k < 40; ++k) s = fmaf(h_sh[k], W2[k * 20 + o], s);
        d_sh[o] = fmaxf(s, 0.f);
    }
    __syncthreads();

    // -- exclusive prefix over earlier chunks (L2-resident aggregates) --------
    float pm0 = -CUDART_INF_F, pm1 = pm0, pm2 = pm0, pm3 = pm0;
    float ps0 = 0.f, ps1 = 0.f, ps2 = 0.f, ps3 = 0.f;
    int pa0 = 0, pa1 = 0, pa2 = 0, pa3 = 0;
    const int base = ((i * NB + n) * J) * CC + 4 * l;
    for (int k = 0; k < j; ++k) {
        float4 m = *(const float4*)&g_cmax[base + k * CC];
        int4   a = *(const int4*)  &g_carg[base + k * CC];
        float4 s = *(const float4*)&g_csum[base + k * CC];
        if (m.x > pm0) { pm0 = m.x; pa0 = a.x; }
        if (m.y > pm1) { pm1 = m.y; pa1 = a.y; }
        if (m.z > pm2) { pm2 = m.z; pa2 = a.z; }
        if (m.w > pm3) { pm3 = m.w; pa3 = a.w; }
        ps0 += s.x; ps1 += s.y; ps2 += s.z; ps3 += s.w;
    }

    const size_t row0 = (size_t)n * LT + (size_t)j * TC;
    const float4* p = (const float4*)(x + row0 * CC) + l;

    float* obase = out + row0 * OUTW + (size_t)i * 384 + 4 * l;
    float* ibase = out + OUT_ELEMS + (size_t)i * NLC + row0 * CC + 4 * l;
    float* abase = ibase + 3 * NLC;

    const float inv_L = 1.0f / (float)LT;

#pragma unroll 2
    for (int t = 0; t < TC; ++t) {
        const int T = j * TC + t;
        float4 v = p[t * 32];
        ps0 += v.x; ps1 += v.y; ps2 += v.z; ps3 += v.w;
        if (v.x > pm0) { pm0 = v.x; pa0 = T; }
        if (v.y > pm1) { pm1 = v.y; pa1 = T; }
        if (v.z > pm2) { pm2 = v.z; pa2 = T; }
        if (v.w > pm3) { pm3 = v.w; pa3 = T; }

        const bool pad = (T < LT - 1);        // window still contains left-pad zeros
        const float padi = (float)(T - (LT - 1));
        float4 pmax = make_float4(pad ? fmaxf(pm0, 0.f) : pm0,
                                  pad ? fmaxf(pm1, 0.f) : pm1,
                                  pad ? fmaxf(pm2, 0.f) : pm2,
                                  pad ? fmaxf(pm3, 0.f) : pm3);
        float4 ind = make_float4((pad && pm0 < 0.f) ? padi : (float)pa0,
                                 (pad && pm1 < 0.f) ? padi : (float)pa1,
                                 (pad && pm2 < 0.f) ? padi : (float)pa2,
                                 (pad && pm3 < 0.f) ? padi : (float)pa3);
        float4 pavg = make_float4(ps0 * inv_L, ps1 * inv_L, ps2 * inv_L, ps3 * inv_L);
        const float rc = __frcp_rn((float)(T + 1));
        float4 psum = make_float4(ps0 * rc, ps1 * rc, ps2 * rc, ps3 * rc);

        float* orow = obase + (size_t)t * OUTW;
        *(float4*)(orow)        = pmax;
        *(float4*)(orow + 128)  = pavg;
        *(float4*)(orow + 256)  = psum;
        *(float4*)(ibase + t * CC) = ind;
        *(float4*)(abase + t * CC) = pmax;
    }

    // -- demographic broadcast cols [1152:1172), written once (i==0 blocks) ---
    if (i == 0) {
        float4 dv[5];
#pragma unroll
        for (int g = 0; g < 5; ++g)
            dv[g] = *(const float4*)&d_sh[4 * g];
        // warp w covers its chunk's 128 rows x 5 float4 groups
        for (int q = l; q < TC * 5; q += 32) {
            const int t = q / 5, g = q % 5;
            *(float4*)(out + (row0 + t) * OUTW + 1152 + 4 * g) = dv[g];
        }
    }
}

extern "C" void kernel_launch(void* const* d_in, const int* in_sizes, int n_in,
                              void* d_out, int out_size) {
    const float* inp0 = (const float*)d_in[0];
    const float* inp1 = (const float*)d_in[1];
    const float* inp2 = (const float*)d_in[2];
    const float* dem  = (const float*)d_in[3];
    const float* W1   = (const float*)d_in[4];
    const float* b1   = (const float*)d_in[5];
    const float* W2   = (const float*)d_in[6];
    const float* b2   = (const float*)d_in[7];
    float* out = (float*)d_out;

    dim3 grid(J / 4, NB, 3);   // 4 x 32 x 3 = 384 blocks, warp per chunk
    agg_kernel<<<grid, 128>>>(inp0, inp1, inp2);
    emit_kernel<<<grid, 128>>>(inp0, inp1, inp2, dem, W1, b1, W2, b2, out);
}

// round 6
// speedup vs baseline: 1.0571x; 1.0334x over previous
#include <cuda_runtime.h>
#include <math_constants.h>

#define NB   32
#define LT   2048
#define CC   128
#define J    64          // chunks along L
#define TC   (LT / J)    // 32 rows per chunk
#define WPB  8           // warps per block (one chunk per warp)
#define OUTW 1172        // 3*384 + 20
#define NLC  ((size_t)NB * LT * CC)          // 8,388,608
#define OUT_ELEMS ((size_t)NB * LT * OUTW)   // 76,808,192

// chunk aggregates: [3][32][J][128] (c contiguous)
__device__ float g_cmax[3 * NB * J * CC];
__device__ int   g_carg[3 * NB * J * CC];
__device__ float g_csum[3 * NB * J * CC];

// ---------------- pass A: per-chunk aggregates (warp per chunk, float4/lane) --
__global__ void __launch_bounds__(32 * WPB) agg_kernel(const float* __restrict__ x0,
                                                       const float* __restrict__ x1,
                                                       const float* __restrict__ x2) {
    const int w = threadIdx.x >> 5;
    const int l = threadIdx.x & 31;
    const int j = blockIdx.x * WPB + w;
    const int n = blockIdx.y, i = blockIdx.z;
    const float* x = (i == 0) ? x0 : (i == 1) ? x1 : x2;
    const float4* p = (const float4*)(x + ((size_t)n * LT + (size_t)j * TC) * CC) + l;

    float m0 = -CUDART_INF_F, m1 = m0, m2 = m0, m3 = m0;
    float s0 = 0.f, s1 = 0.f, s2 = 0.f, s3 = 0.f;
    int a0 = 0, a1 = 0, a2 = 0, a3 = 0;
#pragma unroll 8
    for (int t = 0; t < TC; ++t) {
        float4 v = p[t * 32];
        const int T = j * TC + t;
        s0 += v.x; s1 += v.y; s2 += v.z; s3 += v.w;
        if (v.x > m0) { m0 = v.x; a0 = T; }
        if (v.y > m1) { m1 = v.y; a1 = T; }
        if (v.z > m2) { m2 = v.z; a2 = T; }
        if (v.w > m3) { m3 = v.w; a3 = T; }
    }
    const int idx = ((i * NB + n) * J + j) * CC + 4 * l;
    *(float4*)&g_cmax[idx] = make_float4(m0, m1, m2, m3);
    *(int4*)  &g_carg[idx] = make_int4(a0, a1, a2, a3);
    *(float4*)&g_csum[idx] = make_float4(s0, s1, s2, s3);
}

// ---------------- pass B: fold prefix, emit all outputs -----------------------
__global__ void __launch_bounds__(32 * WPB) emit_kernel(const float* __restrict__ x0,
                                                        const float* __restrict__ x1,
                                                        const float* __restrict__ x2,
                                                        const float* __restrict__ dem,
                                                        const float* __restrict__ W1,
                                                        const float* __restrict__ b1,
                                                        const float* __restrict__ W2,
                                                        const float* __restrict__ b2,
                                                        float* __restrict__ out) {
    const int w = threadIdx.x >> 5;
    const int l = threadIdx.x & 31;
    const int j = blockIdx.x * WPB + w;
    const int n = blockIdx.y, i = blockIdx.z;
    const float* x = (i == 0) ? x0 : (i == 1) ? x1 : x2;

    // -- demographic MLP (only needed by i==0 blocks; recomputed per block) ----
    __shared__ float h_sh[40];
    __shared__ float d_sh[20];
    if (i == 0 && threadIdx.x < 40) {
        const int o = threadIdx.x;
        float s = b1[o];
#pragma unroll
        for (int k = 0; k < 8; ++k) s = fmaf(dem[n * 8 + k], W1[k * 40 + o], s);
        h_sh[o] = fmaxf(s, 0.f);
    }
    __syncthreads();
    if (i == 0 && threadIdx.x < 20) {
        const int o = threadIdx.x;
        float s = b2[o];
#pragma unroll
        for (int k = 0; k < 40; ++k) s = fmaf(h_sh[k], W2[k * 20 + o], s);
        d_sh[o] = fmaxf(s, 0.f);
    }
    __syncthreads();

    // -- exclusive prefix over earlier chunks (L2-resident aggregates) --------
    float pm0 = -CUDART_INF_F, pm1 = pm0, pm2 = pm0, pm3 = pm0;
    float ps0 = 0.f, ps1 = 0.f, ps2 = 0.f, ps3 = 0.f;
    int pa0 = 0, pa1 = 0, pa2 = 0, pa3 = 0;
    const int base = ((i * NB + n) * J) * CC + 4 * l;
#pragma unroll 4
    for (int k = 0; k < j; ++k) {
        float4 m = *(const float4*)&g_cmax[base + k * CC];
        int4   a = *(const int4*)  &g_carg[base + k * CC];
        float4 s = *(const float4*)&g_csum[base + k * CC];
        if (m.x > pm0) { pm0 = m.x; pa0 = a.x; }
        if (m.y > pm1) { pm1 = m.y; pa1 = a.y; }
        if (m.z > pm2) { pm2 = m.z; pa2 = a.z; }
        if (m.w > pm3) { pm3 = m.w; pa3 = a.w; }
        ps0 += s.x; ps1 += s.y; ps2 += s.z; ps3 += s.w;
    }

    const size_t row0 = (size_t)n * LT + (size_t)j * TC;
    const float4* p = (const float4*)(x + row0 * CC) + l;

    float* obase = out + row0 * OUTW + (size_t)i * 384 + 4 * l;
    float* ibase = out + OUT_ELEMS + (size_t)i * NLC + row0 * CC + 4 * l;
    float* abase = ibase + 3 * NLC;

    const float inv_L = 1.0f / (float)LT;

#pragma unroll 4
    for (int t = 0; t < TC; ++t) {
        const int T = j * TC + t;
        float4 v = p[t * 32];
        ps0 += v.x; ps1 += v.y; ps2 += v.z; ps3 += v.w;
        if (v.x > pm0) { pm0 = v.x; pa0 = T; }
        if (v.y > pm1) { pm1 = v.y; pa1 = T; }
        if (v.z > pm2) { pm2 = v.z; pa2 = T; }
        if (v.w > pm3) { pm3 = v.w; pa3 = T; }

        const bool pad = (T < LT - 1);        // window still contains left-pad zeros
        const float padi = (float)(T - (LT - 1));
        float4 pmax = make_float4(pad ? fmaxf(pm0, 0.f) : pm0,
                                  pad ? fmaxf(pm1, 0.f) : pm1,
                                  pad ? fmaxf(pm2, 0.f) : pm2,
                                  pad ? fmaxf(pm3, 0.f) : pm3);
        float4 ind = make_float4((pad && pm0 < 0.f) ? padi : (float)pa0,
                                 (pad && pm1 < 0.f) ? padi : (float)pa1,
                                 (pad && pm2 < 0.f) ? padi : (float)pa2,
                                 (pad && pm3 < 0.f) ? padi : (float)pa3);
        float4 pavg = make_float4(ps0 * inv_L, ps1 * inv_L, ps2 * inv_L, ps3 * inv_L);
        const float rc = __frcp_rn((float)(T + 1));
        float4 psum = make_float4(ps0 * rc, ps1 * rc, ps2 * rc, ps3 * rc);

        float* orow = obase + (size_t)t * OUTW;
        __stcs((float4*)(orow),        pmax);
        __stcs((float4*)(orow + 128),  pavg);
        __stcs((float4*)(orow + 256),  psum);
        __stcs((float4*)(ibase + t * CC), ind);
        __stcs((float4*)(abase + t * CC), pmax);
    }

    // -- demographic broadcast cols [1152:1172), written once (i==0 blocks) ---
    if (i == 0) {
        float4 dv[5];
#pragma unroll
        for (int g = 0; g < 5; ++g)
            dv[g] = *(const float4*)&d_sh[4 * g];
#pragma unroll
        for (int q = l; q < TC * 5; q += 32) {
            const int t = q / 5, g = q % 5;
            __stcs((float4*)(out + (row0 + t) * OUTW + 1152 + 4 * g), dv[g]);
        }
    }
}

extern "C" void kernel_launch(void* const* d_in, const int* in_sizes, int n_in,
                              void* d_out, int out_size) {
    const float* inp0 = (const float*)d_in[0];
    const float* inp1 = (const float*)d_in[1];
    const float* inp2 = (const float*)d_in[2];
    const float* dem  = (const float*)d_in[3];
    const float* W1   = (const float*)d_in[4];
    const float* b1   = (const float*)d_in[5];
    const float* W2   = (const float*)d_in[6];
    const float* b2   = (const float*)d_in[7];
    float* out = (float*)d_out;

    dim3 grid(J / WPB, NB, 3);   // 8 x 32 x 3 = 768 blocks, warp per chunk
    agg_kernel<<<grid, 32 * WPB>>>(inp0, inp1, inp2);
    emit_kernel<<<grid, 32 * WPB>>>(inp0, inp1, inp2, dem, W1, b1, W2, b2, out);
}